// round 9
// baseline (speedup 1.0000x reference)
#include <cuda_runtime.h>
#include <cuda_fp16.h>
#include <cstdint>

// ---------------------------------------------------------------------------
// CliffordLinear via Cl(3,0) ~= M2(C) (Pauli).  One real fp16 GEMM
// M=16384, N=1024, K=1024 (HALF the MACs of the dense blade embedding).
// Legacy HMMA rate is ~1 instr/3.5cyc/SM (measured) and the mainloop is
// pipe-saturated; this round removes wave quantization:
//   kernel1: 888 tiles (128x128) = exactly 3 waves at 2 CTAs/SM
//   kernel2: tail strip re-tiled as 272 tiles (64x128) = 1 wave
// ---------------------------------------------------------------------------

#define B_DIM 8192
#define CIN  256
#define COUT 256
#define M_GEMM 16384
#define N_GEMM 1024
#define K_GEMM 1024

#define M1_TILES 111                 /* kernel1 m-tiles: 111*128 = 14208 rows */
#define M_SPLIT  (M1_TILES * 128)
#define M2_TILES ((M_GEMM - M_SPLIT) / 64)   /* 34 */

__device__ __half g_Ah[M_GEMM * K_GEMM];   // 32 MB
__device__ __half g_Bh[N_GEMM * K_GEMM];   // 2 MB

// ---------------------------------------------------------------------------
// Prologue 1: x -> A matrix.  One thread per (b,i).
// ---------------------------------------------------------------------------
__global__ void __launch_bounds__(1024) a_transform_kernel(const float4* __restrict__ x4) {
    int t = blockIdx.x * 1024 + threadIdx.x;       // 0 .. B*CIN-1
    float4 v0 = x4[2 * t];                          // x0..x3
    float4 v1 = x4[2 * t + 1];                      // x4..x7
    int b = t >> 8, i = t & 255;
    __half2* A = reinterpret_cast<__half2*>(g_Ah);
    A[(2 * b    ) * 512 +       i] = __floats2half2_rn(v0.x + v1.x, v0.y + v1.y);
    A[(2 * b    ) * 512 + 256 + i] = __floats2half2_rn(v0.w + v1.w, v0.z + v1.z);
    A[(2 * b + 1) * 512 +       i] = __floats2half2_rn(v0.y - v1.y, v0.x - v1.x);
    A[(2 * b + 1) * 512 + 256 + i] = __floats2half2_rn(v1.z - v0.z, v1.w - v0.w);
}

// ---------------------------------------------------------------------------
// Prologue 2: weight -> B matrix.  One thread per (o,i).
// ---------------------------------------------------------------------------
__global__ void __launch_bounds__(1024) b_transform_kernel(const float* __restrict__ w) {
    int t = blockIdx.x * 1024 + threadIdx.x;       // 0 .. COUT*CIN-1
    int o = t >> 8, i = t & 255;
    const float* p = w + (size_t)t * 8;
    float w0 = p[0], w1 = p[1], w2 = p[2], w3 = p[3];
    float w4 = p[4], w5 = p[5], w6 = p[6], w7 = p[7];
    float Rm00 = .5f * (w0 + w4), Rm01 = .5f * (w1 - w5);
    float Rm10 = .5f * (w1 + w5), Rm11 = .5f * (w0 - w4);
    float Im00 = .5f * (w3 + w7), Im01 = .5f * (w6 - w2);
    float Im10 = .5f * (w2 + w6), Im11 = .5f * (w7 - w3);
    __half2* Bm = reinterpret_cast<__half2*>(g_Bh);
    int n0 = 4 * o;
    Bm[(n0    ) * 512 +       i] = __floats2half2_rn( Rm00,  Rm01);
    Bm[(n0    ) * 512 + 256 + i] = __floats2half2_rn(-Im00, -Im01);
    Bm[(n0 + 1) * 512 +       i] = __floats2half2_rn( Rm10,  Rm11);
    Bm[(n0 + 1) * 512 + 256 + i] = __floats2half2_rn(-Im10, -Im11);
    Bm[(n0 + 2) * 512 +       i] = __floats2half2_rn( Im00,  Im01);
    Bm[(n0 + 2) * 512 + 256 + i] = __floats2half2_rn( Rm00,  Rm01);
    Bm[(n0 + 3) * 512 +       i] = __floats2half2_rn( Im10,  Im11);
    Bm[(n0 + 3) * 512 + 256 + i] = __floats2half2_rn( Rm10,  Rm11);
}

// ---------------------------------------------------------------------------
// Shared GEMM machinery
// ---------------------------------------------------------------------------
#define BKP_H 72
#define ROW_B (BKP_H * 2)                  /* 144 bytes per smem row */
#define NSTAGES 3
#define NUM_ITERS (K_GEMM / 64)            /* 16 */

__device__ __forceinline__ void mma_f16(float& c0, float& c1, float& c2, float& c3,
                                        uint32_t a0, uint32_t a1, uint32_t a2, uint32_t a3,
                                        uint32_t b0, uint32_t b1) {
    asm volatile(
        "mma.sync.aligned.m16n8k16.row.col.f32.f16.f16.f32 "
        "{%0,%1,%2,%3}, {%4,%5,%6,%7}, {%8,%9}, {%0,%1,%2,%3};"
        : "+f"(c0), "+f"(c1), "+f"(c2), "+f"(c3)
        : "r"(a0), "r"(a1), "r"(a2), "r"(a3), "r"(b0), "r"(b1));
}

// Inner compute for one stage: warp tile 64x32 (mi=4, ni=4).
// aP/bP point at this thread's fragment base within the stage.
#define COMPUTE_STAGE(aP, bP)                                                         \
    _Pragma("unroll")                                                                 \
    for (int q = 0; q < 2; q++) {                                                     \
        uint4 fb[4];                                                                  \
        _Pragma("unroll")                                                             \
        for (int ni = 0; ni < 4; ni++)                                                \
            fb[ni] = *reinterpret_cast<const uint4*>((bP) + ni * 8 * BKP_H + 8 * q);  \
        _Pragma("unroll")                                                             \
        for (int mi = 0; mi < 4; mi++) {                                              \
            uint4 fa0 = *reinterpret_cast<const uint4*>((aP) + (mi * 16    ) * BKP_H + 8 * q); \
            uint4 fa1 = *reinterpret_cast<const uint4*>((aP) + (mi * 16 + 8) * BKP_H + 8 * q); \
            const uint32_t* pa0 = &fa0.x;                                             \
            const uint32_t* pa1 = &fa1.x;                                             \
            _Pragma("unroll")                                                         \
            for (int kk = 0; kk < 2; kk++) {                                          \
                uint32_t a0 = pa0[2 * kk], a2 = pa0[2 * kk + 1];                      \
                uint32_t a1 = pa1[2 * kk], a3 = pa1[2 * kk + 1];                      \
                _Pragma("unroll")                                                     \
                for (int ni = 0; ni < 4; ni++) {                                      \
                    const uint32_t* pb = &fb[ni].x;                                   \
                    mma_f16(acc[mi][ni][0], acc[mi][ni][1],                           \
                            acc[mi][ni][2], acc[mi][ni][3],                           \
                            a0, a1, a2, a3, pb[2 * kk], pb[2 * kk + 1]);              \
                }                                                                     \
            }                                                                         \
        }                                                                             \
    }

// Epilogue: stage warp tile to smem, rebuild blades, +bias, store.
// Warp tile rows = 64 (32 b x 2 c), cols = 32 (8 o x 4).
#define EPS 34
#define EPILOGUE(ep_base, b_glob, o0)                                                 \
    {                                                                                 \
        float* ep = (ep_base);                                                        \
        _Pragma("unroll")                                                             \
        for (int mi = 0; mi < 4; mi++)                                                \
            _Pragma("unroll")                                                         \
            for (int ni = 0; ni < 4; ni++) {                                          \
                float2 v0 = make_float2(acc[mi][ni][0], acc[mi][ni][1]);              \
                float2 v1 = make_float2(acc[mi][ni][2], acc[mi][ni][3]);              \
                *reinterpret_cast<float2*>(ep + (mi * 16 + lr    ) * EPS + ni * 8 + 2 * lc) = v0; \
                *reinterpret_cast<float2*>(ep + (mi * 16 + lr + 8) * EPS + ni * 8 + 2 * lc) = v1; \
            }                                                                         \
        __syncwarp();                                                                 \
        float* Crow = C + (size_t)(b_glob) * (COUT * 8);                              \
        const float* rowA = ep + (2 * lane) * EPS;                                    \
        const float* rowB = rowA + EPS;                                               \
        _Pragma("unroll")                                                             \
        for (int ol = 0; ol < 8; ol++) {                                              \
            float A0 = rowA[4 * ol], A1 = rowA[4 * ol + 1];                           \
            float A2 = rowA[4 * ol + 2], A3 = rowA[4 * ol + 3];                       \
            float B0 = rowB[4 * ol], B1 = rowB[4 * ol + 1];                           \
            float B2 = rowB[4 * ol + 2], B3 = rowB[4 * ol + 3];                       \
            int o = (o0) + ol;                                                        \
            float4 bv0 = *reinterpret_cast<const float4*>(bias + o * 8);              \
            float4 bv1 = *reinterpret_cast<const float4*>(bias + o * 8 + 4);          \
            float4 u, v;                                                              \
            u.x = A0 + B1 + bv0.x;  u.y = B0 + A1 + bv0.y;                            \
            u.z = A3 - B2 + bv0.z;  u.w = A2 - B3 + bv0.w;                            \
            v.x = A0 - B1 + bv1.x;  v.y = A1 - B0 + bv1.y;                            \
            v.z = B2 + A3 + bv1.z;  v.w = A2 + B3 + bv1.w;                            \
            *reinterpret_cast<float4*>(Crow + o * 8    ) = u;                         \
            *reinterpret_cast<float4*>(Crow + o * 8 + 4) = v;                         \
        }                                                                             \
    }

// ---------------------------------------------------------------------------
// Kernel 1: BM=128, BN=128, 256 threads (2x4 warps of 64x32). 888 CTAs.
// ---------------------------------------------------------------------------
#define K1_TILE_BYTES (128 * ROW_B)            /* 18432 */
#define K1_STAGE (2 * K1_TILE_BYTES)           /* 36864 */
#define K1_SMEM (NSTAGES * K1_STAGE)           /* 110592 */

__global__ void __launch_bounds__(256, 2) gemm_main_kernel(
    const float* __restrict__ bias, float* __restrict__ C)
{
    extern __shared__ __half smem[];
    const int tid  = threadIdx.x;
    const int wid  = tid >> 5;
    const int lane = tid & 31;
    const int wm = wid & 1, wn = wid >> 1;
    const int lr = lane >> 2, lc = lane & 3;
    const int block_m = blockIdx.y * 128;
    const int block_n = blockIdx.x * 128;

    uint32_t smem_u;
    asm("{ .reg .u64 t; cvta.to.shared.u64 t, %1; cvt.u32.u64 %0, t; }"
        : "=r"(smem_u) : "l"(smem));

    const int r0 = tid >> 3;                     // 0..31
    const int q0 = tid & 7;
    const uint32_t u0 = (uint32_t)(r0 * ROW_B + q0 * 16);
    const __half* gA = g_Ah + (size_t)(block_m + r0) * K_GEMM + q0 * 8;
    const __half* gB = g_Bh + (size_t)(block_n + r0) * K_GEMM + q0 * 8;

#define K1_LOAD(sbase, pA, pB) do {                                                   \
        _Pragma("unroll")                                                             \
        for (int t_ = 0; t_ < 4; t_++) {                                              \
            asm volatile("cp.async.cg.shared.global [%0], [%1], 16;"                  \
                :: "r"((sbase) + (uint32_t)(t_ * 32 * ROW_B)),                        \
                   "l"((pA) + (size_t)t_ * 32 * K_GEMM));                             \
            asm volatile("cp.async.cg.shared.global [%0], [%1], 16;"                  \
                :: "r"((sbase) + (uint32_t)(t_ * 32 * ROW_B + K1_TILE_BYTES)),        \
                   "l"((pB) + (size_t)t_ * 32 * K_GEMM));                             \
        }                                                                             \
    } while (0)

    float acc[4][4][4];
#pragma unroll
    for (int mi = 0; mi < 4; mi++)
#pragma unroll
        for (int ni = 0; ni < 4; ni++)
#pragma unroll
            for (int q = 0; q < 4; q++) acc[mi][ni][q] = 0.0f;

    K1_LOAD(smem_u + u0, gA, gB);
    asm volatile("cp.async.commit_group;" ::: "memory");
    K1_LOAD(smem_u + K1_STAGE + u0, gA + 64, gB + 64);
    asm volatile("cp.async.commit_group;" ::: "memory");

    const __half* gA_run = gA + 128;
    const __half* gB_run = gB + 128;

    const int aOff = (wm * 64 + lr) * BKP_H + 16 * lc;
    const int bOff = 128 * BKP_H + (wn * 32 + lr) * BKP_H + 16 * lc;

    int sc = 0, sl = 2;
    for (int it = 0; it < NUM_ITERS; ++it) {
        asm volatile("cp.async.wait_group 1;" ::: "memory");
        __syncthreads();
        if (it + 2 < NUM_ITERS)
            K1_LOAD(smem_u + (uint32_t)sl * K1_STAGE + u0, gA_run, gB_run);
        asm volatile("cp.async.commit_group;" ::: "memory");
        gA_run += 64; gB_run += 64;

        const __half* As = smem + sc * (K1_STAGE / 2);
        const __half* aP = As + aOff;
        const __half* bP = As + bOff;
        COMPUTE_STAGE(aP, bP);
        sc = (sc == NSTAGES - 1) ? 0 : sc + 1;
        sl = (sl == NSTAGES - 1) ? 0 : sl + 1;
    }

    asm volatile("cp.async.wait_group 0;" ::: "memory");
    __syncthreads();
    EPILOGUE(reinterpret_cast<float*>(smem) + wid * (64 * EPS),
             block_m / 2 + wm * 32 + lane,
             block_n / 4 + wn * 8);
}

// ---------------------------------------------------------------------------
// Kernel 2 (tail strip): BM=64, BN=128, 128 threads (1x4 warps of 64x32).
// 34 x 8 = 272 CTAs = one wave.
// ---------------------------------------------------------------------------
#define K2_A_BYTES (64 * ROW_B)                /* 9216  */
#define K2_STAGE (K2_A_BYTES + 128 * ROW_B)    /* 27648 */
#define K2_SMEM (NSTAGES * K2_STAGE)           /* 82944 */

__global__ void __launch_bounds__(128, 2) gemm_tail_kernel(
    const float* __restrict__ bias, float* __restrict__ C)
{
    extern __shared__ __half smem[];
    const int tid  = threadIdx.x;
    const int wid  = tid >> 5;                  // 0..3
    const int lane = tid & 31;
    const int wn = wid;                         // wm = 0
    const int lr = lane >> 2, lc = lane & 3;
    const int block_m = M_SPLIT + blockIdx.y * 64;
    const int block_n = blockIdx.x * 128;

    uint32_t smem_u;
    asm("{ .reg .u64 t; cvta.to.shared.u64 t, %1; cvt.u32.u64 %0, t; }"
        : "=r"(smem_u) : "l"(smem));

    const int r0 = tid >> 3;                    // 0..15
    const int q0 = tid & 7;
    const uint32_t u0 = (uint32_t)(r0 * ROW_B + q0 * 16);
    const __half* gA = g_Ah + (size_t)(block_m + r0) * K_GEMM + q0 * 8;
    const __half* gB = g_Bh + (size_t)(block_n + r0) * K_GEMM + q0 * 8;

#define K2_LOAD(sbase, pA, pB) do {                                                   \
        _Pragma("unroll")                                                             \
        for (int t_ = 0; t_ < 4; t_++)                                                \
            asm volatile("cp.async.cg.shared.global [%0], [%1], 16;"                  \
                :: "r"((sbase) + (uint32_t)(t_ * 16 * ROW_B)),                        \
                   "l"((pA) + (size_t)t_ * 16 * K_GEMM));                             \
        _Pragma("unroll")                                                             \
        for (int t_ = 0; t_ < 8; t_++)                                                \
            asm volatile("cp.async.cg.shared.global [%0], [%1], 16;"                  \
                :: "r"((sbase) + (uint32_t)(t_ * 16 * ROW_B + K2_A_BYTES)),           \
                   "l"((pB) + (size_t)t_ * 16 * K_GEMM));                             \
    } while (0)

    float acc[4][4][4];
#pragma unroll
    for (int mi = 0; mi < 4; mi++)
#pragma unroll
        for (int ni = 0; ni < 4; ni++)
#pragma unroll
            for (int q = 0; q < 4; q++) acc[mi][ni][q] = 0.0f;

    K2_LOAD(smem_u + u0, gA, gB);
    asm volatile("cp.async.commit_group;" ::: "memory");
    K2_LOAD(smem_u + K2_STAGE + u0, gA + 64, gB + 64);
    asm volatile("cp.async.commit_group;" ::: "memory");

    const __half* gA_run = gA + 128;
    const __half* gB_run = gB + 128;

    const int aOff = lr * BKP_H + 16 * lc;                       // wm = 0
    const int bOff = 64 * BKP_H + (wn * 32 + lr) * BKP_H + 16 * lc;

    int sc = 0, sl = 2;
    for (int it = 0; it < NUM_ITERS; ++it) {
        asm volatile("cp.async.wait_group 1;" ::: "memory");
        __syncthreads();
        if (it + 2 < NUM_ITERS)
            K2_LOAD(smem_u + (uint32_t)sl * K2_STAGE + u0, gA_run, gB_run);
        asm volatile("cp.async.commit_group;" ::: "memory");
        gA_run += 64; gB_run += 64;

        const __half* As = smem + sc * (K2_STAGE / 2);
        const __half* aP = As + aOff;
        const __half* bP = As + bOff;
        COMPUTE_STAGE(aP, bP);
        sc = (sc == NSTAGES - 1) ? 0 : sc + 1;
        sl = (sl == NSTAGES - 1) ? 0 : sl + 1;
    }

    asm volatile("cp.async.wait_group 0;" ::: "memory");
    __syncthreads();
    EPILOGUE(reinterpret_cast<float*>(smem) + wid * (64 * EPS),
             block_m / 2 + lane,
             block_n / 4 + wn * 8);
}

// ---------------------------------------------------------------------------
// Launch.  Inputs: x, weight, bias, cayley (metadata order).
// ---------------------------------------------------------------------------
extern "C" void kernel_launch(void* const* d_in, const int* in_sizes, int n_in,
                              void* d_out, int out_size) {
    const float* x      = (const float*)d_in[0];   // [8192, 256, 8]
    const float* weight = (const float*)d_in[1];   // [256, 256, 8]
    const float* bias   = (const float*)d_in[2];   // [256, 8]
    float* out = (float*)d_out;                    // [8192, 256, 8]
    (void)in_sizes; (void)n_in; (void)out_size;

    a_transform_kernel<<<(B_DIM * CIN) / 1024, 1024>>>((const float4*)x);
    b_transform_kernel<<<(COUT * CIN) / 1024, 1024>>>(weight);

    cudaFuncSetAttribute(gemm_main_kernel,
                         cudaFuncAttributeMaxDynamicSharedMemorySize, K1_SMEM);
    cudaFuncSetAttribute(gemm_tail_kernel,
                         cudaFuncAttributeMaxDynamicSharedMemorySize, K2_SMEM);

    dim3 grid1(N_GEMM / 128, M1_TILES);        // (8, 111) = 888 CTAs
    gemm_main_kernel<<<grid1, 256, K1_SMEM>>>(bias, out);

    dim3 grid2(N_GEMM / 128, M2_TILES);        // (8, 34) = 272 CTAs
    gemm_tail_kernel<<<grid2, 128, K2_SMEM>>>(bias, out);
}

// round 12
// speedup vs baseline: 1.0397x; 1.0397x over previous
#include <cuda_runtime.h>
#include <cuda_fp16.h>
#include <cstdint>

// ---------------------------------------------------------------------------
// CliffordLinear via Cl(3,0) ~= M2(C) (Pauli).  One real fp16 GEMM
// M=16384, N=1024, K=1024 (HALF the MACs of the dense blade embedding).
// Single fused launch: 888 CTAs of 128x128 tiles (3 exact waves at 2/SM)
// + 272 CTAs of 64x128 tail tiles that fill the drain of the last wave.
// ---------------------------------------------------------------------------

#define B_DIM 8192
#define CIN  256
#define COUT 256
#define M_GEMM 16384
#define N_GEMM 1024
#define K_GEMM 1024

#define M1_TILES 111                 /* main m-tiles: 111*128 = 14208 rows */
#define M_SPLIT  (M1_TILES * 128)
#define MAIN_CTAS (M1_TILES * 8)     /* 888 */
#define M2_TILES ((M_GEMM - M_SPLIT) / 64)   /* 34 */
#define TAIL_CTAS (M2_TILES * 8)     /* 272 */

__device__ __half g_Ah[M_GEMM * K_GEMM];   // 32 MB
__device__ __half g_Bh[N_GEMM * K_GEMM];   // 2 MB

// ---------------------------------------------------------------------------
// Prologue 1: x -> A matrix.  One thread per (b,i).
// ---------------------------------------------------------------------------
__global__ void __launch_bounds__(1024) a_transform_kernel(const float4* __restrict__ x4) {
    int t = blockIdx.x * 1024 + threadIdx.x;       // 0 .. B*CIN-1
    float4 v0 = x4[2 * t];                          // x0..x3
    float4 v1 = x4[2 * t + 1];                      // x4..x7
    int b = t >> 8, i = t & 255;
    __half2* A = reinterpret_cast<__half2*>(g_Ah);
    A[(2 * b    ) * 512 +       i] = __floats2half2_rn(v0.x + v1.x, v0.y + v1.y);
    A[(2 * b    ) * 512 + 256 + i] = __floats2half2_rn(v0.w + v1.w, v0.z + v1.z);
    A[(2 * b + 1) * 512 +       i] = __floats2half2_rn(v0.y - v1.y, v0.x - v1.x);
    A[(2 * b + 1) * 512 + 256 + i] = __floats2half2_rn(v1.z - v0.z, v1.w - v0.w);
}

// ---------------------------------------------------------------------------
// Prologue 2: weight -> B matrix.  One thread per (o,i).
// ---------------------------------------------------------------------------
__global__ void __launch_bounds__(1024) b_transform_kernel(const float* __restrict__ w) {
    int t = blockIdx.x * 1024 + threadIdx.x;       // 0 .. COUT*CIN-1
    int o = t >> 8, i = t & 255;
    const float* p = w + (size_t)t * 8;
    float w0 = p[0], w1 = p[1], w2 = p[2], w3 = p[3];
    float w4 = p[4], w5 = p[5], w6 = p[6], w7 = p[7];
    float Rm00 = .5f * (w0 + w4), Rm01 = .5f * (w1 - w5);
    float Rm10 = .5f * (w1 + w5), Rm11 = .5f * (w0 - w4);
    float Im00 = .5f * (w3 + w7), Im01 = .5f * (w6 - w2);
    float Im10 = .5f * (w2 + w6), Im11 = .5f * (w7 - w3);
    __half2* Bm = reinterpret_cast<__half2*>(g_Bh);
    int n0 = 4 * o;
    Bm[(n0    ) * 512 +       i] = __floats2half2_rn( Rm00,  Rm01);
    Bm[(n0    ) * 512 + 256 + i] = __floats2half2_rn(-Im00, -Im01);
    Bm[(n0 + 1) * 512 +       i] = __floats2half2_rn( Rm10,  Rm11);
    Bm[(n0 + 1) * 512 + 256 + i] = __floats2half2_rn(-Im10, -Im11);
    Bm[(n0 + 2) * 512 +       i] = __floats2half2_rn( Im00,  Im01);
    Bm[(n0 + 2) * 512 + 256 + i] = __floats2half2_rn( Rm00,  Rm01);
    Bm[(n0 + 3) * 512 +       i] = __floats2half2_rn( Im10,  Im11);
    Bm[(n0 + 3) * 512 + 256 + i] = __floats2half2_rn( Rm10,  Rm11);
}

// ---------------------------------------------------------------------------
// Shared GEMM machinery
// ---------------------------------------------------------------------------
#define BKP_H 72
#define ROW_B (BKP_H * 2)                  /* 144 bytes per smem row */
#define NSTAGES 3
#define NUM_ITERS (K_GEMM / 64)            /* 16 */

__device__ __forceinline__ void mma_f16(float& c0, float& c1, float& c2, float& c3,
                                        uint32_t a0, uint32_t a1, uint32_t a2, uint32_t a3,
                                        uint32_t b0, uint32_t b1) {
    asm volatile(
        "mma.sync.aligned.m16n8k16.row.col.f32.f16.f16.f32 "
        "{%0,%1,%2,%3}, {%4,%5,%6,%7}, {%8,%9}, {%0,%1,%2,%3};"
        : "+f"(c0), "+f"(c1), "+f"(c2), "+f"(c3)
        : "r"(a0), "r"(a1), "r"(a2), "r"(a3), "r"(b0), "r"(b1));
}

// Inner compute for one stage: warp tile (MI*16) x 32.
#define COMPUTE_STAGE(aP, bP, MI)                                                     \
    _Pragma("unroll")                                                                 \
    for (int q = 0; q < 2; q++) {                                                     \
        uint4 fb[4];                                                                  \
        _Pragma("unroll")                                                             \
        for (int ni = 0; ni < 4; ni++)                                                \
            fb[ni] = *reinterpret_cast<const uint4*>((bP) + ni * 8 * BKP_H + 8 * q);  \
        _Pragma("unroll")                                                             \
        for (int mi = 0; mi < (MI); mi++) {                                           \
            uint4 fa0 = *reinterpret_cast<const uint4*>((aP) + (mi * 16    ) * BKP_H + 8 * q); \
            uint4 fa1 = *reinterpret_cast<const uint4*>((aP) + (mi * 16 + 8) * BKP_H + 8 * q); \
            const uint32_t* pa0 = &fa0.x;                                             \
            const uint32_t* pa1 = &fa1.x;                                             \
            _Pragma("unroll")                                                         \
            for (int kk = 0; kk < 2; kk++) {                                          \
                uint32_t a0 = pa0[2 * kk], a2 = pa0[2 * kk + 1];                      \
                uint32_t a1 = pa1[2 * kk], a3 = pa1[2 * kk + 1];                      \
                _Pragma("unroll")                                                     \
                for (int ni = 0; ni < 4; ni++) {                                      \
                    const uint32_t* pb = &fb[ni].x;                                   \
                    mma_f16(acc[mi][ni][0], acc[mi][ni][1],                           \
                            acc[mi][ni][2], acc[mi][ni][3],                           \
                            a0, a1, a2, a3, pb[2 * kk], pb[2 * kk + 1]);              \
                }                                                                     \
            }                                                                         \
        }                                                                             \
    }

// Blade reconstruction for one (b, o): A* = row c=0, B* = row c=1 values.
#define BLADE_STORE(Crow, o, A0, A1, A2, A3, B0, B1, B2, B3)                          \
    {                                                                                 \
        float4 bv0 = *reinterpret_cast<const float4*>(bias + (o) * 8);                \
        float4 bv1 = *reinterpret_cast<const float4*>(bias + (o) * 8 + 4);            \
        float4 u, v;                                                                  \
        u.x = A0 + B1 + bv0.x;  u.y = B0 + A1 + bv0.y;                                \
        u.z = A3 - B2 + bv0.z;  u.w = A2 - B3 + bv0.w;                                \
        v.x = A0 - B1 + bv1.x;  v.y = A1 - B0 + bv1.y;                                \
        v.z = B2 + A3 + bv1.z;  v.w = A2 + B3 + bv1.w;                                \
        *reinterpret_cast<float4*>((Crow) + (o) * 8    ) = u;                         \
        *reinterpret_cast<float4*>((Crow) + (o) * 8 + 4) = v;                         \
    }

#define EPS 34

#define K1_TILE_BYTES (128 * ROW_B)            /* 18432 */
#define K1_STAGE (2 * K1_TILE_BYTES)           /* 36864 */
#define K1_SMEM (NSTAGES * K1_STAGE)           /* 110592 */

#define K2_A_BYTES (64 * ROW_B)                /* 9216  */
#define K2_STAGE (K2_A_BYTES + 128 * ROW_B)    /* 27648 */

// ---------------------------------------------------------------------------
// Main path: BM=128, BN=128, 2x4 warps of 64x32.
// ---------------------------------------------------------------------------
__device__ __forceinline__ void main_path(
    __half* smem, uint32_t smem_u, const float* __restrict__ bias,
    float* __restrict__ C, int bid)
{
    const int tid  = threadIdx.x;
    const int wid  = tid >> 5;
    const int lane = tid & 31;
    const int wm = wid & 1, wn = wid >> 1;
    const int lr = lane >> 2, lc = lane & 3;
    const int block_m = (bid >> 3) * 128;
    const int block_n = (bid & 7) * 128;

    const int r0 = tid >> 3;                     // 0..31
    const int q0 = tid & 7;
    const uint32_t u0 = (uint32_t)(r0 * ROW_B + q0 * 16);
    const __half* gA = g_Ah + (size_t)(block_m + r0) * K_GEMM + q0 * 8;
    const __half* gB = g_Bh + (size_t)(block_n + r0) * K_GEMM + q0 * 8;

#define K1_LOAD(sbase, pA, pB) do {                                                   \
        _Pragma("unroll")                                                             \
        for (int t_ = 0; t_ < 4; t_++) {                                              \
            asm volatile("cp.async.cg.shared.global [%0], [%1], 16;"                  \
                :: "r"((sbase) + (uint32_t)(t_ * 32 * ROW_B)),                        \
                   "l"((pA) + (size_t)t_ * 32 * K_GEMM));                             \
            asm volatile("cp.async.cg.shared.global [%0], [%1], 16;"                  \
                :: "r"((sbase) + (uint32_t)(t_ * 32 * ROW_B + K1_TILE_BYTES)),        \
                   "l"((pB) + (size_t)t_ * 32 * K_GEMM));                             \
        }                                                                             \
    } while (0)

    float acc[4][4][4];
#pragma unroll
    for (int mi = 0; mi < 4; mi++)
#pragma unroll
        for (int ni = 0; ni < 4; ni++)
#pragma unroll
            for (int q = 0; q < 4; q++) acc[mi][ni][q] = 0.0f;

    K1_LOAD(smem_u + u0, gA, gB);
    asm volatile("cp.async.commit_group;" ::: "memory");
    K1_LOAD(smem_u + K1_STAGE + u0, gA + 64, gB + 64);
    asm volatile("cp.async.commit_group;" ::: "memory");

    const __half* gA_run = gA + 128;
    const __half* gB_run = gB + 128;

    const int aOff = (wm * 64 + lr) * BKP_H + 16 * lc;
    const int bOff = 128 * BKP_H + (wn * 32 + lr) * BKP_H + 16 * lc;

    int sc = 0, sl = 2;
    for (int it = 0; it < NUM_ITERS; ++it) {
        asm volatile("cp.async.wait_group 1;" ::: "memory");
        __syncthreads();
        if (it + 2 < NUM_ITERS)
            K1_LOAD(smem_u + (uint32_t)sl * K1_STAGE + u0, gA_run, gB_run);
        asm volatile("cp.async.commit_group;" ::: "memory");
        gA_run += 64; gB_run += 64;

        const __half* As = smem + sc * (K1_STAGE / 2);
        COMPUTE_STAGE(As + aOff, As + bOff, 4);
        sc = (sc == NSTAGES - 1) ? 0 : sc + 1;
        sl = (sl == NSTAGES - 1) ? 0 : sl + 1;
    }

    asm volatile("cp.async.wait_group 0;" ::: "memory");
    __syncthreads();

    // epilogue: 64-row warp tile (32 b x 2 c), 32 cols (8 o x 4)
    float* ep = reinterpret_cast<float*>(smem) + wid * (64 * EPS);
#pragma unroll
    for (int mi = 0; mi < 4; mi++)
#pragma unroll
        for (int ni = 0; ni < 4; ni++) {
            *reinterpret_cast<float2*>(ep + (mi * 16 + lr    ) * EPS + ni * 8 + 2 * lc) =
                make_float2(acc[mi][ni][0], acc[mi][ni][1]);
            *reinterpret_cast<float2*>(ep + (mi * 16 + lr + 8) * EPS + ni * 8 + 2 * lc) =
                make_float2(acc[mi][ni][2], acc[mi][ni][3]);
        }
    __syncwarp();
    const int b_glob = block_m / 2 + wm * 32 + lane;
    const int o0 = block_n / 4 + wn * 8;
    float* Crow = C + (size_t)b_glob * (COUT * 8);
    const float* rowA = ep + (2 * lane) * EPS;
    const float* rowB = rowA + EPS;
#pragma unroll
    for (int ol = 0; ol < 8; ol++)
        BLADE_STORE(Crow, o0 + ol,
                    rowA[4 * ol], rowA[4 * ol + 1], rowA[4 * ol + 2], rowA[4 * ol + 3],
                    rowB[4 * ol], rowB[4 * ol + 1], rowB[4 * ol + 2], rowB[4 * ol + 3]);
}

// ---------------------------------------------------------------------------
// Tail path: BM=64, BN=128, 2x4 warps of 32x32.
// ---------------------------------------------------------------------------
__device__ __forceinline__ void tail_path(
    __half* smem, uint32_t smem_u, const float* __restrict__ bias,
    float* __restrict__ C, int bid)
{
    const int tid  = threadIdx.x;
    const int wid  = tid >> 5;
    const int lane = tid & 31;
    const int wm = wid & 1, wn = wid >> 1;
    const int lr = lane >> 2, lc = lane & 3;
    const int block_m = M_SPLIT + (bid >> 3) * 64;
    const int block_n = (bid & 7) * 128;

    const int r0 = tid >> 3;                     // 0..31
    const int q0 = tid & 7;
    const uint32_t u0 = (uint32_t)(r0 * ROW_B + q0 * 16);
    const __half* gA = g_Ah + (size_t)(block_m + r0) * K_GEMM + q0 * 8;
    const __half* gB = g_Bh + (size_t)(block_n + r0) * K_GEMM + q0 * 8;

#define K2_LOAD(sbase, pA, pB) do {                                                   \
        _Pragma("unroll")                                                             \
        for (int t_ = 0; t_ < 2; t_++)                                                \
            asm volatile("cp.async.cg.shared.global [%0], [%1], 16;"                  \
                :: "r"((sbase) + (uint32_t)(t_ * 32 * ROW_B)),                        \
                   "l"((pA) + (size_t)t_ * 32 * K_GEMM));                             \
        _Pragma("unroll")                                                             \
        for (int t_ = 0; t_ < 4; t_++)                                                \
            asm volatile("cp.async.cg.shared.global [%0], [%1], 16;"                  \
                :: "r"((sbase) + (uint32_t)(t_ * 32 * ROW_B + K2_A_BYTES)),           \
                   "l"((pB) + (size_t)t_ * 32 * K_GEMM));                             \
    } while (0)

    float acc[2][4][4];
#pragma unroll
    for (int mi = 0; mi < 2; mi++)
#pragma unroll
        for (int ni = 0; ni < 4; ni++)
#pragma unroll
            for (int q = 0; q < 4; q++) acc[mi][ni][q] = 0.0f;

    K2_LOAD(smem_u + u0, gA, gB);
    asm volatile("cp.async.commit_group;" ::: "memory");
    K2_LOAD(smem_u + K2_STAGE + u0, gA + 64, gB + 64);
    asm volatile("cp.async.commit_group;" ::: "memory");

    const __half* gA_run = gA + 128;
    const __half* gB_run = gB + 128;

    const int aOff = (wm * 32 + lr) * BKP_H + 16 * lc;
    const int bOff = 64 * BKP_H + (wn * 32 + lr) * BKP_H + 16 * lc;

    int sc = 0, sl = 2;
    for (int it = 0; it < NUM_ITERS; ++it) {
        asm volatile("cp.async.wait_group 1;" ::: "memory");
        __syncthreads();
        if (it + 2 < NUM_ITERS)
            K2_LOAD(smem_u + (uint32_t)sl * K2_STAGE + u0, gA_run, gB_run);
        asm volatile("cp.async.commit_group;" ::: "memory");
        gA_run += 64; gB_run += 64;

        const __half* As = smem + sc * (K2_STAGE / 2);
        COMPUTE_STAGE(As + aOff, As + bOff, 2);
        sc = (sc == NSTAGES - 1) ? 0 : sc + 1;
        sl = (sl == NSTAGES - 1) ? 0 : sl + 1;
    }

    asm volatile("cp.async.wait_group 0;" ::: "memory");
    __syncthreads();

    // epilogue: 32-row warp tile (16 b x 2 c), 32 cols (8 o x 4)
    float* ep = reinterpret_cast<float*>(smem) + wid * (32 * EPS);
#pragma unroll
    for (int mi = 0; mi < 2; mi++)
#pragma unroll
        for (int ni = 0; ni < 4; ni++) {
            *reinterpret_cast<float2*>(ep + (mi * 16 + lr    ) * EPS + ni * 8 + 2 * lc) =
                make_float2(acc[mi][ni][0], acc[mi][ni][1]);
            *reinterpret_cast<float2*>(ep + (mi * 16 + lr + 8) * EPS + ni * 8 + 2 * lc) =
                make_float2(acc[mi][ni][2], acc[mi][ni][3]);
        }
    __syncwarp();
    if (lane < 16) {
        const int b_glob = block_m / 2 + wm * 16 + lane;
        const int o0 = block_n / 4 + wn * 8;
        float* Crow = C + (size_t)b_glob * (COUT * 8);
        const float* rowA = ep + (2 * lane) * EPS;
        const float* rowB = rowA + EPS;
#pragma unroll
        for (int ol = 0; ol < 8; ol++)
            BLADE_STORE(Crow, o0 + ol,
                        rowA[4 * ol], rowA[4 * ol + 1], rowA[4 * ol + 2], rowA[4 * ol + 3],
                        rowB[4 * ol], rowB[4 * ol + 1], rowB[4 * ol + 2], rowB[4 * ol + 3]);
    }
}

// ---------------------------------------------------------------------------
// Fused GEMM kernel: CTAs [0,888) main, [888,1160) tail.
// ---------------------------------------------------------------------------
__global__ void __launch_bounds__(256, 2) gemm_fused_kernel(
    const float* __restrict__ bias, float* __restrict__ C)
{
    extern __shared__ __half smem[];
    uint32_t smem_u;
    asm("{ .reg .u64 t; cvta.to.shared.u64 t, %1; cvt.u32.u64 %0, t; }"
        : "=r"(smem_u) : "l"(smem));

    int bid = blockIdx.x;
    if (bid < MAIN_CTAS)
        main_path(smem, smem_u, bias, C, bid);
    else
        tail_path(smem, smem_u, bias, C, bid - MAIN_CTAS);
}

// ---------------------------------------------------------------------------
// Launch.  Inputs: x, weight, bias, cayley (metadata order).
// ---------------------------------------------------------------------------
extern "C" void kernel_launch(void* const* d_in, const int* in_sizes, int n_in,
                              void* d_out, int out_size) {
    const float* x      = (const float*)d_in[0];   // [8192, 256, 8]
    const float* weight = (const float*)d_in[1];   // [256, 256, 8]
    const float* bias   = (const float*)d_in[2];   // [256, 8]
    float* out = (float*)d_out;                    // [8192, 256, 8]
    (void)in_sizes; (void)n_in; (void)out_size;

    a_transform_kernel<<<(B_DIM * CIN) / 1024, 1024>>>((const float4*)x);
    b_transform_kernel<<<(COUT * CIN) / 1024, 1024>>>(weight);

    cudaFuncSetAttribute(gemm_fused_kernel,
                         cudaFuncAttributeMaxDynamicSharedMemorySize, K1_SMEM);
    gemm_fused_kernel<<<MAIN_CTAS + TAIL_CTAS, 256, K1_SMEM>>>(bias, out);
}